// round 1
// baseline (speedup 1.0000x reference)
#include <cuda_runtime.h>
#include <cuda_bf16.h>
#include <math.h>

// Problem constants
#define BB 8
#define SS 4096
#define DD 256
#define HH 8
#define HD 32
#define LL 4
#define MM (BB*SS)          // 32768 rows
#define EPSLN 1e-5f
#define ATTN_SCALE 0.015625f  // 1/sqrt(4096) = 1/64

// -------- scratch (device globals; no runtime allocation) --------
__device__ float  g_out_buf[MM*DD];       // layer output (residual stream)
__device__ float  g_att_buf[MM*DD];       // attended (post-MSA residual)
__device__ float  g_m_buf[MM*DD];         // FFN intermediate
__device__ float  g_qkv_buf[MM*3*DD];     // [Q(256) | K(256) | V(256)] per row
__device__ float2 g_stats[MM];            // (mu, rstd) per row

// ---------------- LN row statistics ----------------
__global__ void ln_stats_kernel(const float* __restrict__ x, float2* __restrict__ stats)
{
    int row  = blockIdx.x * 8 + (threadIdx.x >> 5);
    int lane = threadIdx.x & 31;
    const float* xr = x + (size_t)row * DD;
    float s = 0.f, ss = 0.f;
#pragma unroll
    for (int i = 0; i < 8; i++) {
        float v = xr[lane + 32*i];
        s += v; ss += v*v;
    }
#pragma unroll
    for (int o = 16; o; o >>= 1) {
        s  += __shfl_xor_sync(0xffffffffu, s,  o);
        ss += __shfl_xor_sync(0xffffffffu, ss, o);
    }
    if (lane == 0) {
        float mu  = s  * (1.f/DD);
        float var = ss * (1.f/DD) - mu*mu;
        stats[row] = make_float2(mu, rsqrtf(var + EPSLN));
    }
}

// ---------------- GELU (exact, matches approximate=False) ----------------
__device__ __forceinline__ float gelu_exact(float x)
{
    return 0.5f * x * (1.f + erff(x * 0.70710678118654752f));
}

// ---------------- SGEMM: C[m,n] = sum_k A'[m,k] * W[n,k] ----------------
// A' = A optionally layer-normalized on load: (a - mu)*rstd*gamma + beta
// EPI: 0 = plain store, 1 = bias+gelu, 2 = bias+gelu+residual
#define BM 128
#define BN 128
#define BK 16

template<int EPI, bool LNA>
__global__ __launch_bounds__(256, 2)
void gemm_kernel(const float* __restrict__ A, const float2* __restrict__ stats,
                 const float* __restrict__ gamma, const float* __restrict__ beta,
                 const float* __restrict__ W, const float* __restrict__ bias,
                 const float* __restrict__ resid, float* __restrict__ C, int ldC)
{
    __shared__ float As[BK][BM];
    __shared__ float Ws[BK][BN];

    const int tid = threadIdx.x;
    const int m0 = blockIdx.x * BM;
    const int n0 = blockIdx.y * BN;
    const int tx = tid & 15;        // 0..15 -> cols tx*8
    const int ty = tid >> 4;        // 0..15 -> rows ty*8

    float acc[8][8];
#pragma unroll
    for (int i = 0; i < 8; i++)
#pragma unroll
        for (int j = 0; j < 8; j++) acc[i][j] = 0.f;

    for (int k0 = 0; k0 < DD; k0 += BK) {
        // load A tile (128 x 16) and W tile (128 x 16), transposed into smem
#pragma unroll
        for (int i = 0; i < 2; i++) {
            int idx = tid + i * 256;        // 0..511
            int r   = idx >> 2;             // 0..127
            int kq  = (idx & 3) << 2;       // 0,4,8,12

            float4 a = *(const float4*)(A + (size_t)(m0 + r) * DD + k0 + kq);
            if (LNA) {
                float2 st = stats[m0 + r];
                float4 g  = *(const float4*)(gamma + k0 + kq);
                float4 be = *(const float4*)(beta  + k0 + kq);
                a.x = (a.x - st.x) * st.y * g.x + be.x;
                a.y = (a.y - st.x) * st.y * g.y + be.y;
                a.z = (a.z - st.x) * st.y * g.z + be.z;
                a.w = (a.w - st.x) * st.y * g.w + be.w;
            }
            As[kq+0][r] = a.x; As[kq+1][r] = a.y;
            As[kq+2][r] = a.z; As[kq+3][r] = a.w;

            float4 w = *(const float4*)(W + (size_t)(n0 + r) * DD + k0 + kq);
            Ws[kq+0][r] = w.x; Ws[kq+1][r] = w.y;
            Ws[kq+2][r] = w.z; Ws[kq+3][r] = w.w;
        }
        __syncthreads();

#pragma unroll
        for (int k = 0; k < BK; k++) {
            float ar[8], br[8];
            *(float4*)(ar)   = *(const float4*)&As[k][ty*8];
            *(float4*)(ar+4) = *(const float4*)&As[k][ty*8+4];
            *(float4*)(br)   = *(const float4*)&Ws[k][tx*8];
            *(float4*)(br+4) = *(const float4*)&Ws[k][tx*8+4];
#pragma unroll
            for (int i = 0; i < 8; i++)
#pragma unroll
                for (int j = 0; j < 8; j++)
                    acc[i][j] += ar[i] * br[j];
        }
        __syncthreads();
    }

    // epilogue
#pragma unroll
    for (int i = 0; i < 8; i++) {
        int m = m0 + ty*8 + i;
#pragma unroll
        for (int jj = 0; jj < 2; jj++) {
            int n = n0 + tx*8 + jj*4;
            float4 v;
            v.x = acc[i][jj*4+0]; v.y = acc[i][jj*4+1];
            v.z = acc[i][jj*4+2]; v.w = acc[i][jj*4+3];
            if (EPI >= 1) {
                float4 bb = *(const float4*)(bias + n);
                v.x = gelu_exact(v.x + bb.x);
                v.y = gelu_exact(v.y + bb.y);
                v.z = gelu_exact(v.z + bb.z);
                v.w = gelu_exact(v.w + bb.w);
            }
            if (EPI == 2) {
                float4 r = *(const float4*)(resid + (size_t)m * DD + n);
                v.x += r.x; v.y += r.y; v.z += r.z; v.w += r.w;
            }
            *(float4*)(C + (size_t)m * ldC + n) = v;
        }
    }
}

// ---------------- diagonal-attention + residual ----------------
// diag[b,h,q] = (1/64) * sum_e Q[b,q,h*32+e] * K[b, e*128+q/32, h*32 + q%32]
// att[b,q,h*32+e] = diag * V[b,q,h*32+e] + cur[b,q,h*32+e]
// One warp handles one (b, h, 32-query block); q%32 == lane.
__global__ void attn_kernel(const float* __restrict__ qkv,
                            const float* __restrict__ cur,
                            float* __restrict__ att)
{
    int w    = blockIdx.x * 8 + (threadIdx.x >> 5);  // global warp id, 0..8191
    int lane = threadIdx.x & 31;
    int qb = w & 127;              // q block (q/32)
    int h  = (w >> 7) & 7;
    int b  = w >> 10;
    int q  = qb * 32 + lane;
    size_t row = (size_t)b * SS + q;

    // load this lane's 32 Q values (contiguous 128B)
    float qv[32];
    const float* qp = qkv + row * 768 + h * 32;
#pragma unroll
    for (int i = 0; i < 8; i++) {
        float4 t = *(const float4*)(qp + 4*i);
        qv[4*i+0] = t.x; qv[4*i+1] = t.y; qv[4*i+2] = t.z; qv[4*i+3] = t.w;
    }

    // gathered K: per e, warp reads 32 consecutive floats (coalesced)
    const float* kbase = qkv + ((size_t)b * SS + qb) * 768 + 256 + h * 32 + lane;
    float diag = 0.f;
#pragma unroll
    for (int e = 0; e < 32; e++)
        diag += qv[e] * kbase[(size_t)e * 128 * 768];
    diag *= ATTN_SCALE;

    const float* vp = qkv + row * 768 + 512 + h * 32;
    const float* rp = cur + row * DD + h * 32;
    float*       op = att + row * DD + h * 32;
#pragma unroll
    for (int i = 0; i < 8; i++) {
        float4 v = *(const float4*)(vp + 4*i);
        float4 r = *(const float4*)(rp + 4*i);
        float4 o;
        o.x = diag * v.x + r.x;
        o.y = diag * v.y + r.y;
        o.z = diag * v.z + r.z;
        o.w = diag * v.w + r.w;
        *(float4*)(op + 4*i) = o;
    }
}

// ---------------- final LN on token 0 of each batch ----------------
__global__ void final_ln_kernel(const float* __restrict__ x,
                                const float* __restrict__ gamma,
                                const float* __restrict__ beta,
                                float* __restrict__ out)
{
    int b    = threadIdx.x >> 5;   // 8 warps, one per batch row
    int lane = threadIdx.x & 31;
    const float* xr = x + (size_t)b * SS * DD;   // token 0 of batch b
    float v[8];
    float s = 0.f, ss = 0.f;
#pragma unroll
    for (int i = 0; i < 8; i++) {
        v[i] = xr[lane + 32*i];
        s += v[i]; ss += v[i]*v[i];
    }
#pragma unroll
    for (int o = 16; o; o >>= 1) {
        s  += __shfl_xor_sync(0xffffffffu, s,  o);
        ss += __shfl_xor_sync(0xffffffffu, ss, o);
    }
    float mu  = __shfl_sync(0xffffffffu, s,  0) * (1.f/DD);
    float ssb = __shfl_sync(0xffffffffu, ss, 0) * (1.f/DD);
    float rs  = rsqrtf(ssb - mu*mu + EPSLN);
#pragma unroll
    for (int i = 0; i < 8; i++) {
        int d = lane + 32*i;
        out[b*DD + d] = (v[i] - mu) * rs * gamma[d] + beta[d];
    }
}

// ---------------- launcher ----------------
extern "C" void kernel_launch(void* const* d_in, const int* in_sizes, int n_in,
                              void* d_out, int out_size)
{
    const float* x     = (const float*)d_in[0];
    const float* Wq    = (const float*)d_in[1];
    const float* Wk    = (const float*)d_in[2];
    const float* Wv    = (const float*)d_in[3];
    const float* W1    = (const float*)d_in[4];
    const float* b1    = (const float*)d_in[5];
    const float* W2    = (const float*)d_in[6];
    const float* b2    = (const float*)d_in[7];
    const float* gamma = (const float*)d_in[8];
    const float* beta  = (const float*)d_in[9];
    float* out = (float*)d_out;

    float  *p_out, *p_att, *p_m, *p_qkv;
    float2 *p_stats;
    cudaGetSymbolAddress((void**)&p_out,   g_out_buf);
    cudaGetSymbolAddress((void**)&p_att,   g_att_buf);
    cudaGetSymbolAddress((void**)&p_m,     g_m_buf);
    cudaGetSymbolAddress((void**)&p_qkv,   g_qkv_buf);
    cudaGetSymbolAddress((void**)&p_stats, g_stats);

    const dim3 gemm_grid(MM / BM, DD / BN);   // (256, 2)

    for (int l = 0; l < LL; l++) {
        const float* cur = (l == 0) ? x : p_out;

        // LN1 stats
        ln_stats_kernel<<<MM/8, 256>>>(cur, p_stats);

        // QKV projections (LN fused into A load)
        gemm_kernel<0, true><<<gemm_grid, 256>>>(cur, p_stats, gamma, beta,
            Wq + (size_t)l*DD*DD, nullptr, nullptr, p_qkv + 0,   768);
        gemm_kernel<0, true><<<gemm_grid, 256>>>(cur, p_stats, gamma, beta,
            Wk + (size_t)l*DD*DD, nullptr, nullptr, p_qkv + 256, 768);
        gemm_kernel<0, true><<<gemm_grid, 256>>>(cur, p_stats, gamma, beta,
            Wv + (size_t)l*DD*DD, nullptr, nullptr, p_qkv + 512, 768);

        // diagonal attention + residual -> attended
        attn_kernel<<<(BB*HH*SS/32)/8, 256>>>(p_qkv, cur, p_att);

        // LN2 stats
        ln_stats_kernel<<<MM/8, 256>>>(p_att, p_stats);

        // FFN1: gelu(LN(att) @ W1^T + b1)
        gemm_kernel<1, true><<<gemm_grid, 256>>>(p_att, p_stats, gamma, beta,
            W1 + (size_t)l*DD*DD, b1 + (size_t)l*DD, nullptr, p_m, DD);

        // FFN2: gelu(m @ W2^T + b2) + attended  (no LN on A)
        gemm_kernel<2, false><<<gemm_grid, 256>>>(p_m, nullptr, nullptr, nullptr,
            W2 + (size_t)l*DD*DD, b2 + (size_t)l*DD, p_att, p_out, DD);
    }

    final_ln_kernel<<<1, 256>>>(p_out, gamma, beta, out);
}

// round 3
// speedup vs baseline: 2.1627x; 2.1627x over previous
#include <cuda_runtime.h>
#include <cuda_bf16.h>
#include <math.h>
#include <cstdint>

#define BB 8
#define SS 4096
#define DD 256
#define LL 4
#define MM (BB*SS)            // 32768 rows
#define EPSLN 1e-5f
#define ATTN_SCALE 0.015625f  // 1/sqrt(4096)
#define WREG (LL*DD*DD)       // 262144 elems per weight family

// ---------------- device scratch ----------------
__device__ float g_out_buf[MM*DD];
__device__ float g_att_buf[MM*DD];
__device__ float g_qkv_buf[MM*3*DD];
__device__ __nv_bfloat16 g_ahi[MM*DD], g_alo[MM*DD];
__device__ __nv_bfloat16 g_mhi[MM*DD], g_mlo[MM*DD];
__device__ __nv_bfloat16 g_whi[5*WREG], g_wlo[5*WREG];

// ---------------- PTX helpers (sm_100-safe: ldmatrix + mma.sync) ----------------
__device__ __forceinline__ uint32_t smem_u32(const void* p) {
    uint32_t a;
    asm("{ .reg .u64 t; cvta.to.shared.u64 t, %1; cvt.u32.u64 %0, t; }" : "=r"(a) : "l"(p));
    return a;
}

__device__ __forceinline__ void ldsm4(uint32_t* r, uint32_t addr) {
    asm volatile("ldmatrix.sync.aligned.m8n8.x4.shared.b16 {%0,%1,%2,%3}, [%4];"
        : "=r"(r[0]), "=r"(r[1]), "=r"(r[2]), "=r"(r[3]) : "r"(addr));
}

__device__ __forceinline__ void mma_bf16(float* c, const uint32_t* a, const uint32_t* b) {
    asm volatile("mma.sync.aligned.m16n8k16.row.col.f32.bf16.bf16.f32 "
        "{%0,%1,%2,%3}, {%4,%5,%6,%7}, {%8,%9}, {%0,%1,%2,%3};"
        : "+f"(c[0]), "+f"(c[1]), "+f"(c[2]), "+f"(c[3])
        : "r"(a[0]), "r"(a[1]), "r"(a[2]), "r"(a[3]), "r"(b[0]), "r"(b[1]));
}

__device__ __forceinline__ float gelu_exact(float x) {
    return 0.5f * x * (1.f + erff(x * 0.70710678118654752f));
}

// ---------------- smem layout: 4 tiles of 128 rows x 64 bf16 (128B rows, swizzled)
#define TILE_B 16384
#define SOFF_AH 0
#define SOFF_AL TILE_B
#define SOFF_BH (2*TILE_B)
#define SOFF_BL (3*TILE_B)
#define GEMM_SMEM (4*TILE_B)

// ---------------- bf16x3 GEMM on mma.sync ----------------
// C[m,n] = sum_k A[m,k]*W[n,k], A=Ahi+Alo, W=Whi+Wlo (bf16, row-major, ld=256)
// EPI: 0 fp32 store (ldC); 1 bias+gelu -> bf16 hi/lo split; 2 bias+gelu+resid fp32
template<int EPI>
__global__ __launch_bounds__(256, 2)
void mma_gemm(const __nv_bfloat16* __restrict__ Ahi, const __nv_bfloat16* __restrict__ Alo,
              const __nv_bfloat16* __restrict__ Whi, const __nv_bfloat16* __restrict__ Wlo,
              const float* __restrict__ bias, const float* __restrict__ resid,
              float* __restrict__ C, int ldC,
              __nv_bfloat16* __restrict__ Ohi, __nv_bfloat16* __restrict__ Olo)
{
    extern __shared__ char smem[];
    const uint32_t sb = smem_u32(smem);
    const int tid  = threadIdx.x;
    const int wid  = tid >> 5;
    const int lane = tid & 31;
    const int warp_m = wid & 3;      // 4 warps along M: 32 rows each
    const int warp_n = wid >> 2;     // 2 warps along N: 64 cols each
    const int m0 = blockIdx.x * 128;
    const int n0 = blockIdx.y * 128;

    float acc[2][8][4];
#pragma unroll
    for (int i = 0; i < 2; i++)
#pragma unroll
        for (int j = 0; j < 8; j++)
#pragma unroll
            for (int q = 0; q < 4; q++) acc[i][j][q] = 0.f;

    // ldmatrix address components (swizzle: chunk col XOR (row&7)<<4)
    const int arow = warp_m * 32 + (lane & 15);            // + mi*16
    const uint32_t acol_x = (uint32_t)((lane >> 4) << 4);  // 0/16 bytes
    const int brow = warp_n * 64 + ((lane >> 4) << 3) + (lane & 7);  // + pi*16
    const uint32_t bcol_x = (uint32_t)(((lane >> 3) & 1) << 4);

    for (int kc = 0; kc < 4; kc++) {
        // ---- load 4 tiles (each 128 rows x 64 bf16) ----
#pragma unroll
        for (int i = 0; i < 4; i++) {
            int idx = i * 256 + tid;                 // 0..1023
            int r = idx >> 3, cb = idx & 7;
            uint32_t so = (uint32_t)(r * 128 + ((cb * 16) ^ ((r & 7) << 4)));
            size_t ga = (size_t)(m0 + r) * DD + kc * 64 + cb * 8;
            size_t gw = (size_t)(n0 + r) * DD + kc * 64 + cb * 8;
            *(uint4*)(smem + SOFF_AH + so) = *(const uint4*)(Ahi + ga);
            *(uint4*)(smem + SOFF_AL + so) = *(const uint4*)(Alo + ga);
            *(uint4*)(smem + SOFF_BH + so) = *(const uint4*)(Whi + gw);
            *(uint4*)(smem + SOFF_BL + so) = *(const uint4*)(Wlo + gw);
        }
        __syncthreads();

#pragma unroll
        for (int ks = 0; ks < 4; ks++) {
            const uint32_t kbyte = (uint32_t)(ks * 32);
            // A fragments (hi & lo) for both m16 tiles
            uint32_t ah[2][4], al[2][4];
#pragma unroll
            for (int mi = 0; mi < 2; mi++) {
                int r = arow + mi * 16;
                uint32_t off = (uint32_t)(r * 128) + ((kbyte + acol_x) ^ ((uint32_t)(r & 7) << 4));
                ldsm4(ah[mi], sb + SOFF_AH + off);
                ldsm4(al[mi], sb + SOFF_AL + off);
            }
#pragma unroll
            for (int pi = 0; pi < 4; pi++) {
                int r = brow + pi * 16;
                uint32_t off = (uint32_t)(r * 128) + ((kbyte + bcol_x) ^ ((uint32_t)(r & 7) << 4));
                uint32_t bh[4], bl[4];
                ldsm4(bh, sb + SOFF_BH + off);
                ldsm4(bl, sb + SOFF_BL + off);
#pragma unroll
                for (int mi = 0; mi < 2; mi++) {
                    mma_bf16(acc[mi][2*pi+0], ah[mi], bh + 0);
                    mma_bf16(acc[mi][2*pi+1], ah[mi], bh + 2);
                    mma_bf16(acc[mi][2*pi+0], ah[mi], bl + 0);
                    mma_bf16(acc[mi][2*pi+1], ah[mi], bl + 2);
                    mma_bf16(acc[mi][2*pi+0], al[mi], bh + 0);
                    mma_bf16(acc[mi][2*pi+1], al[mi], bh + 2);
                }
            }
        }
        __syncthreads();
    }

    // ---- epilogue: thread owns rows (lane>>2, +8), col pair (lane&3)*2 per tile
    const int r0 = (lane >> 2);
    const int c0 = (lane & 3) * 2;
#pragma unroll
    for (int mi = 0; mi < 2; mi++) {
#pragma unroll
        for (int ni = 0; ni < 8; ni++) {
            int n = n0 + warp_n * 64 + ni * 8 + c0;
            int mA = m0 + warp_m * 32 + mi * 16 + r0;
#pragma unroll
            for (int h = 0; h < 2; h++) {      // row halves (+0, +8)
                int m = mA + h * 8;
                float v0 = acc[mi][ni][2*h+0];
                float v1 = acc[mi][ni][2*h+1];
                if constexpr (EPI == 0) {
                    float2 o = make_float2(v0, v1);
                    *(float2*)(C + (size_t)m * ldC + n) = o;
                } else if constexpr (EPI == 1) {
                    v0 = gelu_exact(v0 + bias[n]);
                    v1 = gelu_exact(v1 + bias[n+1]);
                    __nv_bfloat16 h0 = __float2bfloat16(v0);
                    __nv_bfloat16 h1 = __float2bfloat16(v1);
                    __nv_bfloat162 hv; hv.x = h0; hv.y = h1;
                    __nv_bfloat162 lv;
                    lv.x = __float2bfloat16(v0 - __bfloat162float(h0));
                    lv.y = __float2bfloat16(v1 - __bfloat162float(h1));
                    *(__nv_bfloat162*)(Ohi + (size_t)m * DD + n) = hv;
                    *(__nv_bfloat162*)(Olo + (size_t)m * DD + n) = lv;
                } else {
                    float2 rd = *(const float2*)(resid + (size_t)m * DD + n);
                    float2 o;
                    o.x = gelu_exact(v0 + bias[n])   + rd.x;
                    o.y = gelu_exact(v1 + bias[n+1]) + rd.y;
                    *(float2*)(C + (size_t)m * ldC + n) = o;
                }
            }
        }
    }
}

// ---------------- LN + bf16 hi/lo split (one warp per row) ----------------
__global__ void lnsplit_kernel(const float* __restrict__ x,
                               const float* __restrict__ gamma, const float* __restrict__ beta,
                               __nv_bfloat16* __restrict__ hi, __nv_bfloat16* __restrict__ lo)
{
    int row  = blockIdx.x * 8 + (threadIdx.x >> 5);
    int lane = threadIdx.x & 31;
    const float* xr = x + (size_t)row * DD;
    float4 v0 = *(const float4*)(xr + lane * 8);
    float4 v1 = *(const float4*)(xr + lane * 8 + 4);
    float s  = v0.x+v0.y+v0.z+v0.w + v1.x+v1.y+v1.z+v1.w;
    float ss = v0.x*v0.x+v0.y*v0.y+v0.z*v0.z+v0.w*v0.w
             + v1.x*v1.x+v1.y*v1.y+v1.z*v1.z+v1.w*v1.w;
#pragma unroll
    for (int o = 16; o; o >>= 1) {
        s  += __shfl_xor_sync(0xffffffffu, s,  o);
        ss += __shfl_xor_sync(0xffffffffu, ss, o);
    }
    float mu = s * (1.f/DD);
    float rs = rsqrtf(ss * (1.f/DD) - mu*mu + EPSLN);
    float4 g0 = *(const float4*)(gamma + lane * 8);
    float4 g1 = *(const float4*)(gamma + lane * 8 + 4);
    float4 b0 = *(const float4*)(beta  + lane * 8);
    float4 b1 = *(const float4*)(beta  + lane * 8 + 4);
    float n[8];
    n[0]=(v0.x-mu)*rs*g0.x+b0.x; n[1]=(v0.y-mu)*rs*g0.y+b0.y;
    n[2]=(v0.z-mu)*rs*g0.z+b0.z; n[3]=(v0.w-mu)*rs*g0.w+b0.w;
    n[4]=(v1.x-mu)*rs*g1.x+b1.x; n[5]=(v1.y-mu)*rs*g1.y+b1.y;
    n[6]=(v1.z-mu)*rs*g1.z+b1.z; n[7]=(v1.w-mu)*rs*g1.w+b1.w;
    alignas(16) __nv_bfloat16 hb[8], lb[8];
#pragma unroll
    for (int j = 0; j < 8; j++) {
        __nv_bfloat16 h = __float2bfloat16(n[j]);
        hb[j] = h;
        lb[j] = __float2bfloat16(n[j] - __bfloat162float(h));
    }
    *(uint4*)(hi + (size_t)row * DD + lane * 8) = *(uint4*)hb;
    *(uint4*)(lo + (size_t)row * DD + lane * 8) = *(uint4*)lb;
}

// ---------------- weight split ----------------
__global__ void wsplit_kernel(const float* __restrict__ wq, const float* __restrict__ wk,
                              const float* __restrict__ wv, const float* __restrict__ w1,
                              const float* __restrict__ w2,
                              __nv_bfloat16* __restrict__ hi, __nv_bfloat16* __restrict__ lo)
{
    int idx = blockIdx.x * 256 + threadIdx.x;
    int region = idx >> 18;
    int off = idx & 0x3FFFF;
    const float* s = (region == 0) ? wq : (region == 1) ? wk :
                     (region == 2) ? wv : (region == 3) ? w1 : w2;
    float v = s[off];
    __nv_bfloat16 h = __float2bfloat16(v);
    hi[idx] = h;
    lo[idx] = __float2bfloat16(v - __bfloat162float(h));
}

// ---------------- diagonal attention + residual ----------------
__global__ void attn_kernel(const float* __restrict__ qkv,
                            const float* __restrict__ cur,
                            float* __restrict__ att)
{
    int w    = blockIdx.x * 8 + (threadIdx.x >> 5);
    int lane = threadIdx.x & 31;
    int qb = w & 127;
    int h  = (w >> 7) & 7;
    int b  = w >> 10;
    int q  = qb * 32 + lane;
    size_t row = (size_t)b * SS + q;

    float qv[32];
    const float* qp = qkv + row * 768 + h * 32;
#pragma unroll
    for (int i = 0; i < 8; i++) {
        float4 t = *(const float4*)(qp + 4*i);
        qv[4*i+0] = t.x; qv[4*i+1] = t.y; qv[4*i+2] = t.z; qv[4*i+3] = t.w;
    }
    const float* kbase = qkv + ((size_t)b * SS + qb) * 768 + 256 + h * 32 + lane;
    float diag = 0.f;
#pragma unroll
    for (int e = 0; e < 32; e++)
        diag += qv[e] * kbase[(size_t)e * 128 * 768];
    diag *= ATTN_SCALE;

    const float* vp = qkv + row * 768 + 512 + h * 32;
    const float* rp = cur + row * DD + h * 32;
    float*       op = att + row * DD + h * 32;
#pragma unroll
    for (int i = 0; i < 8; i++) {
        float4 v = *(const float4*)(vp + 4*i);
        float4 r = *(const float4*)(rp + 4*i);
        float4 o;
        o.x = diag*v.x + r.x; o.y = diag*v.y + r.y;
        o.z = diag*v.z + r.z; o.w = diag*v.w + r.w;
        *(float4*)(op + 4*i) = o;
    }
}

// ---------------- final LN on token 0 ----------------
__global__ void final_ln_kernel(const float* __restrict__ x,
                                const float* __restrict__ gamma,
                                const float* __restrict__ beta,
                                float* __restrict__ out)
{
    int b    = threadIdx.x >> 5;
    int lane = threadIdx.x & 31;
    const float* xr = x + (size_t)b * SS * DD;
    float v[8];
    float s = 0.f, ss = 0.f;
#pragma unroll
    for (int i = 0; i < 8; i++) {
        v[i] = xr[lane + 32*i];
        s += v[i]; ss += v[i]*v[i];
    }
#pragma unroll
    for (int o = 16; o; o >>= 1) {
        s  += __shfl_xor_sync(0xffffffffu, s,  o);
        ss += __shfl_xor_sync(0xffffffffu, ss, o);
    }
    float mu = s * (1.f/DD);
    float rs = rsqrtf(ss * (1.f/DD) - mu*mu + EPSLN);
#pragma unroll
    for (int i = 0; i < 8; i++) {
        int d = lane + 32*i;
        out[b*DD + d] = (v[i] - mu) * rs * gamma[d] + beta[d];
    }
}

// ---------------- launcher ----------------
extern "C" void kernel_launch(void* const* d_in, const int* in_sizes, int n_in,
                              void* d_out, int out_size)
{
    const float* x     = (const float*)d_in[0];
    const float* Wq    = (const float*)d_in[1];
    const float* Wk    = (const float*)d_in[2];
    const float* Wv    = (const float*)d_in[3];
    const float* W1    = (const float*)d_in[4];
    const float* b1    = (const float*)d_in[5];
    const float* W2    = (const float*)d_in[6];
    const float* b2    = (const float*)d_in[7];
    const float* gamma = (const float*)d_in[8];
    const float* beta  = (const float*)d_in[9];
    float* out = (float*)d_out;

    float *p_out, *p_att, *p_qkv;
    __nv_bfloat16 *p_ahi, *p_alo, *p_mhi, *p_mlo, *p_whi, *p_wlo;
    cudaGetSymbolAddress((void**)&p_out, g_out_buf);
    cudaGetSymbolAddress((void**)&p_att, g_att_buf);
    cudaGetSymbolAddress((void**)&p_qkv, g_qkv_buf);
    cudaGetSymbolAddress((void**)&p_ahi, g_ahi);
    cudaGetSymbolAddress((void**)&p_alo, g_alo);
    cudaGetSymbolAddress((void**)&p_mhi, g_mhi);
    cudaGetSymbolAddress((void**)&p_mlo, g_mlo);
    cudaGetSymbolAddress((void**)&p_whi, g_whi);
    cudaGetSymbolAddress((void**)&p_wlo, g_wlo);

    cudaFuncSetAttribute(mma_gemm<0>, cudaFuncAttributeMaxDynamicSharedMemorySize, GEMM_SMEM);
    cudaFuncSetAttribute(mma_gemm<1>, cudaFuncAttributeMaxDynamicSharedMemorySize, GEMM_SMEM);
    cudaFuncSetAttribute(mma_gemm<2>, cudaFuncAttributeMaxDynamicSharedMemorySize, GEMM_SMEM);

    wsplit_kernel<<<5*WREG/256, 256>>>(Wq, Wk, Wv, W1, W2, p_whi, p_wlo);

    const dim3 grid(MM/128, 2);

    for (int l = 0; l < LL; l++) {
        const float* cur = (l == 0) ? x : p_out;
        size_t wo = (size_t)l * DD * DD;

        lnsplit_kernel<<<MM/8, 256>>>(cur, gamma, beta, p_ahi, p_alo);

        mma_gemm<0><<<grid, 256, GEMM_SMEM>>>(p_ahi, p_alo,
            p_whi + 0*WREG + wo, p_wlo + 0*WREG + wo,
            nullptr, nullptr, p_qkv + 0, 768, nullptr, nullptr);
        mma_gemm<0><<<grid, 256, GEMM_SMEM>>>(p_ahi, p_alo,
            p_whi + 1*WREG + wo, p_wlo + 1*WREG + wo,
            nullptr, nullptr, p_qkv + 256, 768, nullptr, nullptr);
        mma_gemm<0><<<grid, 256, GEMM_SMEM>>>(p_ahi, p_alo,
            p_whi + 2*WREG + wo, p_wlo + 2*WREG + wo,
            nullptr, nullptr, p_qkv + 512, 768, nullptr, nullptr);

        attn_kernel<<<(BB*8*SS/32)/8, 256>>>(p_qkv, cur, p_att);

        lnsplit_kernel<<<MM/8, 256>>>(p_att, gamma, beta, p_ahi, p_alo);

        mma_gemm<1><<<grid, 256, GEMM_SMEM>>>(p_ahi, p_alo,
            p_whi + 3*WREG + wo, p_wlo + 3*WREG + wo,
            b1 + (size_t)l*DD, nullptr, nullptr, 0, p_mhi, p_mlo);

        mma_gemm<2><<<grid, 256, GEMM_SMEM>>>(p_mhi, p_mlo,
            p_whi + 4*WREG + wo, p_wlo + 4*WREG + wo,
            b2 + (size_t)l*DD, p_att, p_out, DD, nullptr, nullptr);
    }

    final_ln_kernel<<<1, 256>>>(p_out, gamma, beta, out);
}